// round 8
// baseline (speedup 1.0000x reference)
#include <cuda_runtime.h>

// CostVolume1D: out[n,d,h,w] = (1/C) * sum_c f1[n,c,h,w] * f2pad[n,c,h,w+d-4]
// f1,f2: [4,128,192,640] fp32. Shuffle-halo float4 kernel (R7) tuned for
// 8 CTAs/SM: launch_bounds(128,8) -> 64-reg cap, unroll 2 (smaller live load
// window), 32-bit indexing (all offsets < 2^31 in float4 units).

#define Nn   4
#define Cc   128
#define Hh   192
#define Ww   640
#define Dd   4
#define NS   (2*Dd + 1)       // 9
#define TPB  128
#define VW   (Ww / 4)         // 160 float4 per row
#define CH4  (Hh * VW)        // channel stride in float4 units (30720)

__global__ __launch_bounds__(TPB, 8)
void costvol1d_kernel(const float4* __restrict__ f1,
                      const float4* __restrict__ f2,
                      float* __restrict__ out)
{
    const int gid  = blockIdx.x * TPB + threadIdx.x;  // 0 .. N*H*VW-1
    const int v    = gid % VW;         // float4 index within row
    const int row  = gid / VW;         // n*Hh + h
    const int n    = row / Hh;
    const int h    = row % Hh;
    const int lane = threadIdx.x & 31;

    // Edge-lane predicated load: lane 0 fetches f2[o-1] (if v>0),
    // lane 31 fetches f2[o+1] (if v<VW-1). Other lanes never load it.
    const bool evalid = (lane == 0) ? (v > 0)
                      : (lane == 31) ? (v < VW - 1) : false;
    const int  eoff   = (lane == 0) ? -1 : 1;

    // 32-bit indexing: max index = 4*128*192*160 = 15,728,640 < 2^31.
    const int base = (n * Cc * Hh + h) * VW + v;   // channel 0

    float acc[NS * 4];
    #pragma unroll
    for (int i = 0; i < NS * 4; i++) acc[i] = 0.0f;

    const float4 z4 = make_float4(0.f, 0.f, 0.f, 0.f);

    #pragma unroll 2
    for (int c = 0; c < Cc; c++) {
        const int o = base + c * CH4;

        const float4 a  = f1[o];
        const float4 c0 = f2[o];
        const float4 e  = evalid ? f2[o + eoff] : z4;

        // Neighbor float4s via warp shuffle of c0 (warp = 32 consecutive v).
        float4 cm, cp;
        cm.x = __shfl_up_sync(0xffffffffu, c0.x, 1);
        cm.y = __shfl_up_sync(0xffffffffu, c0.y, 1);
        cm.z = __shfl_up_sync(0xffffffffu, c0.z, 1);
        cm.w = __shfl_up_sync(0xffffffffu, c0.w, 1);
        cp.x = __shfl_down_sync(0xffffffffu, c0.x, 1);
        cp.y = __shfl_down_sync(0xffffffffu, c0.y, 1);
        cp.z = __shfl_down_sync(0xffffffffu, c0.z, 1);
        cp.w = __shfl_down_sync(0xffffffffu, c0.w, 1);
        if (lane == 0)  cm = e;   // left edge of warp's 32-v span
        if (lane == 31) cp = e;   // right edge

        // window win[k] = f2pad[w-4+k], k=0..11
        float win[12];
        win[0] = cm.x; win[1] = cm.y; win[2]  = cm.z; win[3]  = cm.w;
        win[4] = c0.x; win[5] = c0.y; win[6]  = c0.z; win[7]  = c0.w;
        win[8] = cp.x; win[9] = cp.y; win[10] = cp.z; win[11] = cp.w;

        float av[4];
        av[0] = a.x; av[1] = a.y; av[2] = a.z; av[3] = a.w;

        #pragma unroll
        for (int d = 0; d < NS; d++) {
            #pragma unroll
            for (int j = 0; j < 4; j++) {
                acc[d * 4 + j] = fmaf(av[j], win[j + d], acc[d * 4 + j]);
            }
        }
    }

    // Epilogue: channel mean, float4 stores. out[n][d][h][w..w+3]
    const float inv = 1.0f / (float)Cc;
    float4* o4 = (float4*)out;
    #pragma unroll
    for (int d = 0; d < NS; d++) {
        float4 o;
        o.x = acc[d * 4 + 0] * inv;
        o.y = acc[d * 4 + 1] * inv;
        o.z = acc[d * 4 + 2] * inv;
        o.w = acc[d * 4 + 3] * inv;
        o4[((n * NS + d) * Hh + h) * VW + v] = o;
    }
}

extern "C" void kernel_launch(void* const* d_in, const int* in_sizes, int n_in,
                              void* d_out, int out_size)
{
    const float4* f1 = (const float4*)d_in[0];
    const float4* f2 = (const float4*)d_in[1];
    float* out = (float*)d_out;
    (void)in_sizes; (void)n_in; (void)out_size;

    const int total = Nn * Hh * VW;          // 122880 threads, 1 float4 each
    dim3 grid(total / TPB);                  // 960 blocks (single full wave)
    dim3 block(TPB);
    costvol1d_kernel<<<grid, block>>>(f1, f2, out);
}